// round 11
// baseline (speedup 1.0000x reference)
#include <cuda_runtime.h>
#include <cuda_bf16.h>

// Shapes: pred_logits [16,32,1024,80] (UNUSED), pred_logits_b [16,32,1024,2],
//         pred_boxes [16,32,1024,4], tgt_bbox [16,32,1,4], tgt_ids [512] (UNUSED)
// Output (f32, concatenated): C [512*1024], rows [512], mode_idx [1]

#define NQ  1024
#define NF  512
#define C_SIZE (NF * NQ)
#define TPB 256               // 8 warps; warp w owns queries [128w, 128w+128)

__device__ __align__(16) int g_cnt[NQ];   // zero-init; bincount of selected rows
__device__ unsigned int      g_done;      // zero-init completion counter

// Monotone float -> uint mapping: a < b  <=>  enc(a) < enc(b)
__device__ __forceinline__ unsigned int float_to_ordered(float f) {
    unsigned int u = __float_as_uint(f);
    return (u & 0x80000000u) ? ~u : (u | 0x80000000u);
}

__global__ void __launch_bounds__(TPB, 4)
fused_kernel(const float* __restrict__ logits_b,
             const float* __restrict__ boxes,
             const float* __restrict__ tgt,
             float* __restrict__ out)
{
    const int f    = blockIdx.x;   // frame 0..511
    const int tid  = threadIdx.x;  // 0..255
    const int lane = tid & 31;
    const int wid  = tid >> 5;     // 0..7

    // Target box (cxcywh -> xyxy)
    const float4 tb = reinterpret_cast<const float4*>(tgt)[f];
    const float tx1 = tb.x - 0.5f * tb.z;
    const float ty1 = tb.y - 0.5f * tb.w;
    const float tx2 = tb.x + 0.5f * tb.z;
    const float ty2 = tb.y + 0.5f * tb.w;
    const float area2 = (tx2 - tx1) * (ty2 - ty1);

    const float4* __restrict__ bptr = reinterpret_cast<const float4*>(boxes)    + (size_t)f * NQ;
    const float2* __restrict__ lptr = reinterpret_cast<const float2*>(logits_b) + (size_t)f * NQ;
    float* __restrict__ cptr = out + (size_t)f * NQ;

    // Lane-coalesced layout (proven: L1 wavefronts 16->4 per LDG.128):
    //   q = wid*128 + i*32 + lane
    const int qbase = wid * 128 + lane;
    float4 p[4];
    float2 l[4];
    #pragma unroll
    for (int i = 0; i < 4; i++) {
        p[i] = bptr[qbase + i * 32];
        l[i] = lptr[qbase + i * 32];
    }

    unsigned int obest = 0xFFFFFFFFu;
    int          bestq = 0;

    #pragma unroll
    for (int i = 0; i < 4; i++) {
        const int q = qbase + i * 32;

        const float cost_bbox = fabsf(p[i].x - tb.x) + fabsf(p[i].y - tb.y)
                              + fabsf(p[i].z - tb.z) + fabsf(p[i].w - tb.w);

        const float x1 = p[i].x - 0.5f * p[i].z;
        const float y1 = p[i].y - 0.5f * p[i].w;
        const float x2 = p[i].x + 0.5f * p[i].z;
        const float y2 = p[i].y + 0.5f * p[i].w;
        const float area1 = (x2 - x1) * (y2 - y1);

        const float lt_x = fmaxf(x1, tx1), lt_y = fmaxf(y1, ty1);
        const float rb_x = fminf(x2, tx2), rb_y = fminf(y2, ty2);
        const float iw = fmaxf(rb_x - lt_x, 0.0f);
        const float ih = fmaxf(rb_y - lt_y, 0.0f);
        const float inter = iw * ih;
        const float uni   = area1 + area2 - inter;

        const float cx1 = fminf(x1, tx1), cy1 = fminf(y1, ty1);
        const float cx2 = fmaxf(x2, tx2), cy2 = fmaxf(y2, ty2);
        const float cw = fmaxf(cx2 - cx1, 0.0f);
        const float ch = fmaxf(cy2 - cy1, 0.0f);
        const float areac = cw * ch;

        // giou = inter/uni - (areac-uni)/areac  ==  one fast division
        const float giou_num = inter * areac - (areac - uni) * uni;
        const float giou     = __fdividef(giou_num, uni * areac);

        // -softmax[1] == -1/(1+exp(l0-l1))
        const float cost_class = -__fdividef(1.0f, 1.0f + __expf(l[i].x - l[i].y));

        const float c = 5.0f * cost_bbox + cost_class - 2.0f * giou;
        cptr[q] = c;                               // warp-coalesced STG.32

        const unsigned int oc = float_to_ordered(c);
        if (oc < obest) { obest = oc; bestq = q; } // q increasing per thread
    }

    // Warp argmin: min cost, then min q among cost-ties (exact JAX tie-break)
    const unsigned int wmin = __reduce_min_sync(0xFFFFFFFFu, obest);
    const unsigned int qc   = (obest == wmin) ? (unsigned int)bestq : 0xFFFFFFFFu;
    const unsigned int wq   = __reduce_min_sync(0xFFFFFFFFu, qc);

    __shared__ unsigned long long warp_min[TPB / 32];
    __shared__ int s_last;
    if (lane == 0)
        warp_min[wid] = ((unsigned long long)wmin << 32) | wq;
    __syncthreads();

    if (tid == 0) {
        unsigned long long m = warp_min[0];
        #pragma unroll
        for (int w = 1; w < TPB / 32; w++)
            if (warp_min[w] < m) m = warp_min[w];
        const int q = (int)(m & 0xFFFFFFFFu);
        out[C_SIZE + f] = (float)q;      // rows output

        // Bincount contribution, then release-increment completion counter.
        atomicAdd(&g_cnt[q], 1);
        unsigned int v;
        asm volatile("atom.acq_rel.gpu.global.add.u32 %0, [%1], %2;"
                     : "=r"(v) : "l"(&g_done), "r"(1u) : "memory");
        s_last = (v == NF - 1) ? 1 : 0;
    }
    __syncthreads();

    // ---- Last CTA: argmax over g_cnt with smallest-index tie-break ----
    if (s_last) {
        int mykey = 0;
        #pragma unroll
        for (int i = 0; i < 4; i++) {
            const int bin = tid * 4 + i;
            int c;
            asm volatile("ld.relaxed.gpu.global.s32 %0, [%1];"
                         : "=r"(c) : "l"(&g_cnt[bin]) : "memory");
            const int k = (c << 10) | (NQ - 1 - bin);
            if (k > mykey) mykey = k;
        }
        // reset g_cnt for next graph replay
        #pragma unroll
        for (int i = 0; i < 4; i++) {
            asm volatile("st.relaxed.gpu.global.s32 [%0], %1;"
                         :: "l"(&g_cnt[tid * 4 + i]), "r"(0) : "memory");
        }

        const int wmax = (int)__reduce_max_sync(0xFFFFFFFFu, (unsigned int)mykey);
        __shared__ int warp_max[TPB / 32];
        if (lane == 0) warp_max[wid] = wmax;
        __syncthreads();
        if (tid == 0) {
            int m = warp_max[0];
            #pragma unroll
            for (int w = 1; w < TPB / 32; w++)
                if (warp_max[w] > m) m = warp_max[w];
            const int mode_idx = (NQ - 1) - (m & (NQ - 1));
            out[C_SIZE + NF] = (float)mode_idx;
            g_done = 0;   // reset for next replay
        }
    }
}

extern "C" void kernel_launch(void* const* d_in, const int* in_sizes, int n_in,
                              void* d_out, int out_size)
{
    // metadata order: pred_logits, pred_logits_b, pred_boxes, tgt_bbox, tgt_ids
    const float* logits_b = (const float*)d_in[1];
    const float* boxes    = (const float*)d_in[2];
    const float* tgt      = (const float*)d_in[3];
    float* out = (float*)d_out;

    fused_kernel<<<NF, TPB>>>(logits_b, boxes, tgt, out);
}

// round 12
// speedup vs baseline: 1.0037x; 1.0037x over previous
#include <cuda_runtime.h>
#include <cuda_bf16.h>

// Shapes: pred_logits [16,32,1024,80] (UNUSED), pred_logits_b [16,32,1024,2],
//         pred_boxes [16,32,1024,4], tgt_bbox [16,32,1,4], tgt_ids [512] (UNUSED)
// Output (f32, concatenated): C [512*1024], rows [512], mode_idx [1]

#define NQ  1024
#define NF  512
#define C_SIZE (NF * NQ)
#define TPB 256
#define NCTA (NF / 2)         // 2 frames per CTA -> 256 CTAs

__device__ __align__(16) int g_cnt[NQ];   // zero-init; bincount of selected rows
__device__ unsigned int      g_done;      // zero-init completion counter

// Monotone float -> uint mapping: a < b  <=>  enc(a) < enc(b)
__device__ __forceinline__ unsigned int float_to_ordered(float f) {
    unsigned int u = __float_as_uint(f);
    return (u & 0x80000000u) ? ~u : (u | 0x80000000u);
}

__global__ void __launch_bounds__(TPB, 2)
fused_kernel(const float* __restrict__ logits_b,
             const float* __restrict__ boxes,
             const float* __restrict__ tgt,
             float* __restrict__ out)
{
    const int b    = blockIdx.x;   // 0..255
    const int f0   = b * 2;        // first frame of this CTA
    const int tid  = threadIdx.x;  // 0..255
    const int lane = tid & 31;
    const int wid  = tid >> 5;     // 0..7

    // Lane-coalesced query index within a frame: q = wid*128 + i*32 + lane
    const int qbase = wid * 128 + lane;

    // ---- Front-batch ALL 16 loads (2 frames x (4 box + 4 logit)): 384 B/thread in flight ----
    float4 p0[4], p1[4];
    float2 l0[4], l1[4];
    {
        const float4* __restrict__ bp0 = reinterpret_cast<const float4*>(boxes)    + (size_t)f0 * NQ;
        const float2* __restrict__ lp0 = reinterpret_cast<const float2*>(logits_b) + (size_t)f0 * NQ;
        const float4* __restrict__ bp1 = bp0 + NQ;
        const float2* __restrict__ lp1 = lp0 + NQ;
        #pragma unroll
        for (int i = 0; i < 4; i++) {
            p0[i] = bp0[qbase + i * 32];
            p1[i] = bp1[qbase + i * 32];
            l0[i] = lp0[qbase + i * 32];
            l1[i] = lp1[qbase + i * 32];
        }
    }

    __shared__ unsigned long long warp_min[2][TPB / 32];
    __shared__ int s_last;

    // ---- Process both frames ----
    #pragma unroll
    for (int fr = 0; fr < 2; fr++) {
        const int f = f0 + fr;
        const float4 tb = reinterpret_cast<const float4*>(tgt)[f];
        const float tx1 = tb.x - 0.5f * tb.z;
        const float ty1 = tb.y - 0.5f * tb.w;
        const float tx2 = tb.x + 0.5f * tb.z;
        const float ty2 = tb.y + 0.5f * tb.w;
        const float area2 = (tx2 - tx1) * (ty2 - ty1);

        float* __restrict__ cptr = out + (size_t)f * NQ;

        unsigned int obest = 0xFFFFFFFFu;
        int          bestq = 0;

        #pragma unroll
        for (int i = 0; i < 4; i++) {
            const float4 pp = fr ? p1[i] : p0[i];
            const float2 ll = fr ? l1[i] : l0[i];
            const int q = qbase + i * 32;

            const float cost_bbox = fabsf(pp.x - tb.x) + fabsf(pp.y - tb.y)
                                  + fabsf(pp.z - tb.z) + fabsf(pp.w - tb.w);

            const float x1 = pp.x - 0.5f * pp.z;
            const float y1 = pp.y - 0.5f * pp.w;
            const float x2 = pp.x + 0.5f * pp.z;
            const float y2 = pp.y + 0.5f * pp.w;
            const float area1 = (x2 - x1) * (y2 - y1);

            const float lt_x = fmaxf(x1, tx1), lt_y = fmaxf(y1, ty1);
            const float rb_x = fminf(x2, tx2), rb_y = fminf(y2, ty2);
            const float iw = fmaxf(rb_x - lt_x, 0.0f);
            const float ih = fmaxf(rb_y - lt_y, 0.0f);
            const float inter = iw * ih;
            const float uni   = area1 + area2 - inter;

            const float cx1 = fminf(x1, tx1), cy1 = fminf(y1, ty1);
            const float cx2 = fmaxf(x2, tx2), cy2 = fmaxf(y2, ty2);
            const float cw = fmaxf(cx2 - cx1, 0.0f);
            const float ch = fmaxf(cy2 - cy1, 0.0f);
            const float areac = cw * ch;

            // giou = inter/uni - (areac-uni)/areac  ==  one fast division
            const float giou_num = inter * areac - (areac - uni) * uni;
            const float giou     = __fdividef(giou_num, uni * areac);

            // -softmax[1] == -1/(1+exp(l0-l1))
            const float cost_class = -__fdividef(1.0f, 1.0f + __expf(ll.x - ll.y));

            const float c = 5.0f * cost_bbox + cost_class - 2.0f * giou;
            cptr[q] = c;                               // warp-coalesced STG.32

            const unsigned int oc = float_to_ordered(c);
            if (oc < obest) { obest = oc; bestq = q; } // q increasing per thread
        }

        // Warp argmin: min cost, then min q among cost-ties (exact JAX tie-break)
        const unsigned int wmin = __reduce_min_sync(0xFFFFFFFFu, obest);
        const unsigned int qc   = (obest == wmin) ? (unsigned int)bestq : 0xFFFFFFFFu;
        const unsigned int wq   = __reduce_min_sync(0xFFFFFFFFu, qc);
        if (lane == 0)
            warp_min[fr][wid] = ((unsigned long long)wmin << 32) | wq;
    }

    __syncthreads();

    if (tid == 0) {
        int qsel[2];
        #pragma unroll
        for (int fr = 0; fr < 2; fr++) {
            unsigned long long m = warp_min[fr][0];
            #pragma unroll
            for (int w = 1; w < TPB / 32; w++)
                if (warp_min[fr][w] < m) m = warp_min[fr][w];
            const int q = (int)(m & 0xFFFFFFFFu);
            qsel[fr] = q;
            out[C_SIZE + f0 + fr] = (float)q;   // rows output
        }

        // Bincount contributions, then one release-increment of the counter.
        atomicAdd(&g_cnt[qsel[0]], 1);
        atomicAdd(&g_cnt[qsel[1]], 1);
        unsigned int v;
        asm volatile("atom.acq_rel.gpu.global.add.u32 %0, [%1], %2;"
                     : "=r"(v) : "l"(&g_done), "r"(1u) : "memory");
        s_last = (v == NCTA - 1) ? 1 : 0;
    }
    __syncthreads();

    // ---- Last CTA: argmax over g_cnt with smallest-index tie-break ----
    if (s_last) {
        int mykey = 0;
        #pragma unroll
        for (int i = 0; i < 4; i++) {
            const int bin = tid * 4 + i;
            int c;
            asm volatile("ld.relaxed.gpu.global.s32 %0, [%1];"
                         : "=r"(c) : "l"(&g_cnt[bin]) : "memory");
            const int k = (c << 10) | (NQ - 1 - bin);
            if (k > mykey) mykey = k;
        }
        // reset g_cnt for next graph replay
        #pragma unroll
        for (int i = 0; i < 4; i++) {
            asm volatile("st.relaxed.gpu.global.s32 [%0], %1;"
                         :: "l"(&g_cnt[tid * 4 + i]), "r"(0) : "memory");
        }

        const int wmax = (int)__reduce_max_sync(0xFFFFFFFFu, (unsigned int)mykey);
        __shared__ int warp_max[TPB / 32];
        if (lane == 0) warp_max[wid] = wmax;
        __syncthreads();
        if (tid == 0) {
            int m = warp_max[0];
            #pragma unroll
            for (int w = 1; w < TPB / 32; w++)
                if (warp_max[w] > m) m = warp_max[w];
            const int mode_idx = (NQ - 1) - (m & (NQ - 1));
            out[C_SIZE + NF] = (float)mode_idx;
            g_done = 0;   // reset for next replay
        }
    }
}

extern "C" void kernel_launch(void* const* d_in, const int* in_sizes, int n_in,
                              void* d_out, int out_size)
{
    // metadata order: pred_logits, pred_logits_b, pred_boxes, tgt_bbox, tgt_ids
    const float* logits_b = (const float*)d_in[1];
    const float* boxes    = (const float*)d_in[2];
    const float* tgt      = (const float*)d_in[3];
    float* out = (float*)d_out;

    fused_kernel<<<NCTA, TPB>>>(logits_b, boxes, tgt, out);
}